// round 2
// baseline (speedup 1.0000x reference)
#include <cuda_runtime.h>
#include <math.h>

#define B_N 32768
#define D_N 512
#define K_N 1024
#define L_N 4
#define BM  32
#define TBL 256

#define SMEM_BYTES ((BM*D_N + BM*K_N + 16*256) * sizeof(float))  // 212,992 B

// Scratch (allocation-free rules: __device__ globals)
__device__ float g_zr[(size_t)B_N * D_N];   // residual z, 64 MB
__device__ float g_csq[L_N * K_N];          // per-level ||c||^2

// ---------------------------------------------------------------------------
// c_sq precompute: one warp per codebook row
// ---------------------------------------------------------------------------
__global__ void csq_kernel(const float* __restrict__ cb)
{
    int warp = (blockIdx.x * blockDim.x + threadIdx.x) >> 5;
    int lane = threadIdx.x & 31;
    if (warp >= L_N * K_N) return;
    const float* row = cb + (size_t)warp * D_N;
    float s = 0.f;
    #pragma unroll 4
    for (int i = lane; i < D_N; i += 32) { float v = row[i]; s += v * v; }
    #pragma unroll
    for (int o = 16; o; o >>= 1) s += __shfl_xor_sync(0xffffffffu, s, o);
    if (lane == 0) g_csq[warp] = s;
}

// ---------------------------------------------------------------------------
// Whitening: g_zr = z0 @ W^T   (M=32768, N=512, Kr=512; NT layout)
// CTA tile 64x64, threads 16x16, thread tile 4x4
// ---------------------------------------------------------------------------
__global__ __launch_bounds__(256)
void whiten_kernel(const float* __restrict__ z0, const float* __restrict__ W)
{
    __shared__ float As[16][68];
    __shared__ float Bs[16][68];
    int tid = threadIdx.x;
    int tx = tid & 15, ty = tid >> 4;
    int mb = blockIdx.y * 64, nb = blockIdx.x * 64;
    int lr = tid >> 2;            // 0..63: tile row
    int lk = (tid & 3) << 2;      // 0,4,8,12: k offset

    float acc[4][4];
    #pragma unroll
    for (int i = 0; i < 4; i++)
        #pragma unroll
        for (int j = 0; j < 4; j++) acc[i][j] = 0.f;

    for (int k0 = 0; k0 < D_N; k0 += 16) {
        float4 av = *(const float4*)&z0[(size_t)(mb + lr) * D_N + k0 + lk];
        float4 bv = *(const float4*)&W [(size_t)(nb + lr) * D_N + k0 + lk];
        __syncthreads();
        As[lk+0][lr] = av.x; As[lk+1][lr] = av.y; As[lk+2][lr] = av.z; As[lk+3][lr] = av.w;
        Bs[lk+0][lr] = bv.x; Bs[lk+1][lr] = bv.y; Bs[lk+2][lr] = bv.z; Bs[lk+3][lr] = bv.w;
        __syncthreads();
        #pragma unroll
        for (int k = 0; k < 16; k++) {
            float4 a = *(const float4*)&As[k][ty << 2];
            float4 b = *(const float4*)&Bs[k][tx << 2];
            float aa[4] = {a.x, a.y, a.z, a.w};
            float bb[4] = {b.x, b.y, b.z, b.w};
            #pragma unroll
            for (int i = 0; i < 4; i++)
                #pragma unroll
                for (int j = 0; j < 4; j++) acc[i][j] = fmaf(aa[i], bb[j], acc[i][j]);
        }
    }
    #pragma unroll
    for (int i = 0; i < 4; i++) {
        float4 o = make_float4(acc[i][0], acc[i][1], acc[i][2], acc[i][3]);
        *(float4*)&g_zr[(size_t)(mb + (ty << 2) + i) * D_N + nb + (tx << 2)] = o;
    }
}

// ---------------------------------------------------------------------------
// Fused level kernel: per CTA = 32 rows.
//   Stage A: S = z_resid @ cb^T          (M=32, N=1024, Kr=512)
//   Softmax: p = softmax((2S - c_sq)/tau), write p, keep p in smem
//   Stage B: z_soft = p @ cb             (M=32, N=512, Kr=1024)
//            write z_soft; g_zr -= z_soft
// ---------------------------------------------------------------------------
__global__ __launch_bounds__(TBL, 1)
void level_kernel(const float* __restrict__ cb, int level,
                  const float* __restrict__ tau,
                  float* __restrict__ out_z, float* __restrict__ out_p)
{
    extern __shared__ float sm[];
    float* zs  = sm;                  // [BM][D_N]  64 KB
    float* S   = sm + BM * D_N;       // [BM][K_N] 128 KB
    float* cbs = S + BM * K_N;        // [16][256]  16 KB (also holds csq)

    const float* csq = g_csq + level * K_N;
    int tid = threadIdx.x;
    int bm0 = blockIdx.x * BM;
    int tx = tid & 31;                // 32 n-threads
    int ty = tid >> 5;                // 8 warps -> m
    int m0 = ty * 4;
    float inv_tau = 1.0f / tau[0];

    // ---- load z tile (coalesced, conflict-free) ----
    #pragma unroll
    for (int i = 0; i < 16; i++) {
        int s = tid + i * TBL;        // 0..4095 float4 slots
        int m = s >> 7;
        int d = (s & 127) << 2;
        *(float4*)&zs[m * D_N + d] = *(const float4*)&g_zr[(size_t)(bm0 + m) * D_N + d];
    }
    __syncthreads();

    // ============================ Stage A ============================
    for (int nb = 0; nb < K_N; nb += 256) {
        float acc[4][8];
        #pragma unroll
        for (int i = 0; i < 4; i++)
            #pragma unroll
            for (int j = 0; j < 8; j++) acc[i][j] = 0.f;

        for (int k0 = 0; k0 < D_N; k0 += 16) {
            float4 t[4];
            #pragma unroll
            for (int i = 0; i < 4; i++) {
                int s  = tid + i * TBL;      // 0..1023
                int n  = s >> 2;             // 0..255
                int kq = (s & 3) << 2;       // 0,4,8,12
                t[i] = *(const float4*)&cb[(size_t)(nb + n) * D_N + k0 + kq];
            }
            __syncthreads();
            #pragma unroll
            for (int i = 0; i < 4; i++) {
                int s  = tid + i * TBL;
                int n  = s >> 2;
                int kq = (s & 3) << 2;
                cbs[(kq+0)*256 + n] = t[i].x;
                cbs[(kq+1)*256 + n] = t[i].y;
                cbs[(kq+2)*256 + n] = t[i].z;
                cbs[(kq+3)*256 + n] = t[i].w;
            }
            __syncthreads();
            #pragma unroll
            for (int k = 0; k < 16; k++) {
                float aa[4];
                #pragma unroll
                for (int i = 0; i < 4; i++) aa[i] = zs[(m0 + i) * D_N + k0 + k];
                float4 b0 = *(const float4*)&cbs[k * 256 + tx * 8];
                float4 b1 = *(const float4*)&cbs[k * 256 + tx * 8 + 4];
                float bb[8] = {b0.x, b0.y, b0.z, b0.w, b1.x, b1.y, b1.z, b1.w};
                #pragma unroll
                for (int i = 0; i < 4; i++)
                    #pragma unroll
                    for (int j = 0; j < 8; j++) acc[i][j] = fmaf(aa[i], bb[j], acc[i][j]);
            }
        }
        #pragma unroll
        for (int i = 0; i < 4; i++) {
            float4 o0 = make_float4(acc[i][0], acc[i][1], acc[i][2], acc[i][3]);
            float4 o1 = make_float4(acc[i][4], acc[i][5], acc[i][6], acc[i][7]);
            *(float4*)&S[(m0 + i) * K_N + nb + tx * 8]     = o0;
            *(float4*)&S[(m0 + i) * K_N + nb + tx * 8 + 4] = o1;
        }
    }
    __syncthreads();

    // ---- stage csq into smem ----
    for (int i = tid; i < K_N; i += TBL) cbs[i] = csq[i];
    __syncthreads();

    // ============================ Softmax ============================
    // logit = (2*dot - c_sq)/tau  (z_sq shift cancels in softmax)
    #pragma unroll
    for (int r = 0; r < 4; r++) {
        float* row = &S[(m0 + r) * K_N];
        float lg[32];
        float mx = -3.402823e38f;
        #pragma unroll
        for (int i = 0; i < 32; i++) {
            int n = tx + (i << 5);
            float v = fmaf(2.0f, row[n], -cbs[n]) * inv_tau;
            lg[i] = v;
            mx = fmaxf(mx, v);
        }
        #pragma unroll
        for (int o = 16; o; o >>= 1) mx = fmaxf(mx, __shfl_xor_sync(0xffffffffu, mx, o));
        float sum = 0.f;
        #pragma unroll
        for (int i = 0; i < 32; i++) { float e = __expf(lg[i] - mx); lg[i] = e; sum += e; }
        #pragma unroll
        for (int o = 16; o; o >>= 1) sum += __shfl_xor_sync(0xffffffffu, sum, o);
        float is = 1.0f / sum;
        float* prow = &out_p[(size_t)(bm0 + m0 + r) * K_N];
        #pragma unroll
        for (int i = 0; i < 32; i++) {
            int n = tx + (i << 5);
            float p = lg[i] * is;
            row[n]  = p;       // keep p in smem for stage B
            prow[n] = p;       // output
        }
    }
    __syncthreads();

    // ============================ Stage B ============================
    for (int db = 0; db < 2; db++) {
        int d0 = db * 256;
        float acc[4][8];
        #pragma unroll
        for (int i = 0; i < 4; i++)
            #pragma unroll
            for (int j = 0; j < 8; j++) acc[i][j] = 0.f;

        for (int nc = 0; nc < K_N; nc += 16) {
            float4 t[4];
            #pragma unroll
            for (int i = 0; i < 4; i++) {
                int s  = tid + i * TBL;
                int n  = s >> 6;             // 0..15
                int dq = (s & 63) << 2;      // 0..252
                t[i] = *(const float4*)&cb[(size_t)(nc + n) * D_N + d0 + dq];
            }
            __syncthreads();
            #pragma unroll
            for (int i = 0; i < 4; i++) {
                int s  = tid + i * TBL;
                int n  = s >> 6;
                int dq = (s & 63) << 2;
                *(float4*)&cbs[n * 256 + dq] = t[i];
            }
            __syncthreads();
            #pragma unroll
            for (int n = 0; n < 16; n++) {
                float aa[4];
                #pragma unroll
                for (int i = 0; i < 4; i++) aa[i] = S[(m0 + i) * K_N + nc + n];
                float4 b0 = *(const float4*)&cbs[n * 256 + tx * 8];
                float4 b1 = *(const float4*)&cbs[n * 256 + tx * 8 + 4];
                float bb[8] = {b0.x, b0.y, b0.z, b0.w, b1.x, b1.y, b1.z, b1.w};
                #pragma unroll
                for (int i = 0; i < 4; i++)
                    #pragma unroll
                    for (int j = 0; j < 8; j++) acc[i][j] = fmaf(aa[i], bb[j], acc[i][j]);
            }
        }
        // epilogue: write z_soft, update residual in-place
        #pragma unroll
        for (int i = 0; i < 4; i++) {
            size_t m = (size_t)(bm0 + m0 + i);
            #pragma unroll
            for (int h = 0; h < 2; h++) {
                int d = d0 + tx * 8 + h * 4;
                float4 o = make_float4(acc[i][h*4+0], acc[i][h*4+1], acc[i][h*4+2], acc[i][h*4+3]);
                float4 r = *(const float4*)&zs[(m0 + i) * D_N + d];
                *(float4*)&out_z[m * D_N + d] = o;
                float4 nr = make_float4(r.x - o.x, r.y - o.y, r.z - o.z, r.w - o.w);
                *(float4*)&g_zr[m * D_N + d] = nr;
            }
        }
    }
}

// ---------------------------------------------------------------------------
// kernel_launch: csq -> whiten -> 4 sequential fused level kernels
// Output layout: [ z_soft_levels (L*B*D) | p_levels (L*B*K) ] fp32
// ---------------------------------------------------------------------------
extern "C" void kernel_launch(void* const* d_in, const int* in_sizes, int n_in,
                              void* d_out, int out_size)
{
    const float* z0   = (const float*)d_in[0];
    const float* tau  = (const float*)d_in[1];
    const float* W    = (const float*)d_in[2];
    const float* cbks = (const float*)d_in[3];
    float* out   = (float*)d_out;
    float* out_z = out;
    float* out_p = out + (size_t)L_N * B_N * D_N;

    cudaFuncSetAttribute(level_kernel, cudaFuncAttributeMaxDynamicSharedMemorySize,
                         (int)SMEM_BYTES);

    csq_kernel<<<(L_N * K_N) / 8, 256>>>(cbks);
    whiten_kernel<<<dim3(D_N / 64, B_N / 64), 256>>>(z0, W);
    for (int l = 0; l < L_N; l++) {
        level_kernel<<<B_N / BM, TBL, SMEM_BYTES>>>(
            cbks + (size_t)l * K_N * D_N, l, tau,
            out_z + (size_t)l * B_N * D_N,
            out_p + (size_t)l * B_N * K_N);
    }
}

// round 6
// speedup vs baseline: 3.7719x; 3.7719x over previous
#include <cuda_runtime.h>
#include <cuda_bf16.h>
#include <cstdint>
#include <math.h>

#define B_N 32768
#define D_N 512
#define K_N 1024
#define L_N 4

// smem offsets (bytes). Rows padded to 80B (40 bf16) -> conflict-free ldmatrix.
#define SA_HI 0
#define SA_LO 10240
#define SB0   20480
#define SB1   30720
#define SMISC 40960
#define SMEM_SZ 41472

__device__ float         g_zr   [(size_t)B_N * D_N];
__device__ __nv_bfloat16 g_zr_hi[(size_t)B_N * D_N];
__device__ __nv_bfloat16 g_zr_lo[(size_t)B_N * D_N];
__device__ __nv_bfloat16 g_cb_hi[(size_t)L_N * K_N * D_N];
__device__ __nv_bfloat16 g_cb_lo[(size_t)L_N * K_N * D_N];
__device__ __nv_bfloat16 g_cbT_hi[(size_t)L_N * D_N * K_N];
__device__ __nv_bfloat16 g_cbT_lo[(size_t)L_N * D_N * K_N];
__device__ __nv_bfloat16 g_W_hi[D_N * D_N];
__device__ __nv_bfloat16 g_W_lo[D_N * D_N];
__device__ float         g_csq[L_N * K_N];
__device__ float         g_E[(size_t)B_N * K_N];
__device__ float         g_Spart[(size_t)32 * B_N];

// ---------------- asm helpers ----------------
__device__ __forceinline__ uint32_t smem_u32(const void* p) {
    uint32_t a;
    asm("{ .reg .u64 t; cvta.to.shared.u64 t, %1; cvt.u32.u64 %0, t; }" : "=r"(a) : "l"(p));
    return a;
}
#define LDSM4(R0,R1,R2,R3,ADDR) \
    asm volatile("ldmatrix.sync.aligned.m8n8.x4.shared.b16 {%0,%1,%2,%3}, [%4];" \
        : "=r"(R0),"=r"(R1),"=r"(R2),"=r"(R3) : "r"(ADDR))
#define MMA(ACC,A,B0,B1) \
    asm volatile("mma.sync.aligned.m16n8k16.row.col.f32.bf16.bf16.f32 " \
        "{%0,%1,%2,%3},{%4,%5,%6,%7},{%8,%9},{%0,%1,%2,%3};" \
        : "+f"((ACC)[0]),"+f"((ACC)[1]),"+f"((ACC)[2]),"+f"((ACC)[3]) \
        : "r"((A)[0]),"r"((A)[1]),"r"((A)[2]),"r"((A)[3]),"r"(B0),"r"(B1))
#define CP16(DST,SRC) \
    asm volatile("cp.async.cg.shared.global [%0], [%1], 16;" :: "r"(DST), "l"(SRC))
#define CP_COMMIT() asm volatile("cp.async.commit_group;" ::: "memory")
#define CP_WAIT1()  asm volatile("cp.async.wait_group 1;" ::: "memory")
#define CP_WAIT0()  asm volatile("cp.async.wait_group 0;" ::: "memory")

__device__ __forceinline__ uint32_t pack2(float a, float b) {
    __nv_bfloat162 t = __floats2bfloat162_rn(a, b);
    return *(uint32_t*)&t;
}
__device__ __forceinline__ float bfr(float x) {
    return __bfloat162float(__float2bfloat16_rn(x));
}

__device__ __forceinline__ void compute_chunk(float acc[2][4][4], uint32_t smb,
                                              uint32_t bHi, int wy, int wx, int lane) {
    #pragma unroll
    for (int ks = 0; ks < 2; ks++) {
        uint32_t aH[2][4], aL[2][4], bH[4][2], bL[4][2];
        #pragma unroll
        for (int i = 0; i < 2; i++) {
            uint32_t ar = smb + SA_HI + (uint32_t)(wy*32 + i*16 + (lane & 15))*80
                          + ks*32 + ((lane >> 4) << 4);
            LDSM4(aH[i][0],aH[i][1],aH[i][2],aH[i][3], ar);
            LDSM4(aL[i][0],aL[i][1],aL[i][2],aL[i][3], ar + 10240);
        }
        #pragma unroll
        for (int jj = 0; jj < 2; jj++) {
            uint32_t br = smb + bHi + (uint32_t)(wx*32 + jj*16 + (lane & 15))*80
                          + ks*32 + ((lane >> 4) << 4);
            uint32_t r0,r1,r2,r3;
            LDSM4(r0,r1,r2,r3, br);
            bH[jj*2][0]=r0; bH[jj*2][1]=r2; bH[jj*2+1][0]=r1; bH[jj*2+1][1]=r3;
            LDSM4(r0,r1,r2,r3, br + 5120);
            bL[jj*2][0]=r0; bL[jj*2][1]=r2; bL[jj*2+1][0]=r1; bL[jj*2+1][1]=r3;
        }
        #pragma unroll
        for (int i = 0; i < 2; i++)
            #pragma unroll
            for (int j = 0; j < 4; j++) {
                MMA(acc[i][j], aH[i], bH[j][0], bH[j][1]);
                MMA(acc[i][j], aH[i], bL[j][0], bL[j][1]);
                MMA(acc[i][j], aL[i], bH[j][0], bH[j][1]);
            }
    }
}

__device__ __forceinline__ void cpasync_B(uint32_t smb, uint32_t bHi,
        const __nv_bfloat16* Bh, const __nv_bfloat16* Bl,
        int nb0, int strideB, int kc, int tid) {
    int row = tid >> 2, seg = tid & 3;
    uint32_t dst = smb + bHi + (uint32_t)row*80 + seg*16;
    size_t off = (size_t)(nb0 + row) * strideB + kc*32 + seg*8;
    CP16(dst,        (const char*)(Bh + off));
    CP16(dst + 5120, (const char*)(Bl + off));
}

// ---------------- prep kernels ----------------
__global__ void csq_kernel(const float* __restrict__ cb) {
    int warp = (blockIdx.x * blockDim.x + threadIdx.x) >> 5;
    int lane = threadIdx.x & 31;
    if (warp >= L_N * K_N) return;
    const float* row = cb + (size_t)warp * D_N;
    float s = 0.f;
    #pragma unroll 4
    for (int i = lane; i < D_N; i += 32) { float v = row[i]; s += v * v; }
    #pragma unroll
    for (int o = 16; o; o >>= 1) s += __shfl_xor_sync(0xffffffffu, s, o);
    if (lane == 0) g_csq[warp] = s;
}
__global__ void split_kernel(const float* __restrict__ src,
                             __nv_bfloat16* __restrict__ hi,
                             __nv_bfloat16* __restrict__ lo, int n) {
    int i = blockIdx.x * blockDim.x + threadIdx.x;
    if (i < n) {
        float x = src[i];
        __nv_bfloat16 h = __float2bfloat16_rn(x);
        hi[i] = h;
        lo[i] = __float2bfloat16_rn(x - __bfloat162float(h));
    }
}
__global__ void tsplit_kernel(const float* __restrict__ cb) {
    __shared__ float tile[32][33];
    int l = blockIdx.z;
    int k0 = blockIdx.x * 32, d0 = blockIdx.y * 32;
    int tx = threadIdx.x, ty = threadIdx.y;
    const float* src = cb + (size_t)l * K_N * D_N;
    for (int i = ty; i < 32; i += 8)
        tile[i][tx] = src[(size_t)(k0 + i) * D_N + d0 + tx];
    __syncthreads();
    __nv_bfloat16* th = g_cbT_hi + (size_t)l * D_N * K_N;
    __nv_bfloat16* tl = g_cbT_lo + (size_t)l * D_N * K_N;
    for (int i = ty; i < 32; i += 8) {
        float x = tile[tx][i];
        __nv_bfloat16 h = __float2bfloat16_rn(x);
        size_t o = (size_t)(d0 + i) * K_N + k0 + tx;
        th[o] = h;
        tl[o] = __float2bfloat16_rn(x - __bfloat162float(h));
    }
}

// ---------------- kernel A: logits -> E=exp((2s-csq)/tau) + partial row sums ----
__global__ void __launch_bounds__(256, 2)
logits_kernel(const __nv_bfloat16* __restrict__ cbh,
              const __nv_bfloat16* __restrict__ cbl,
              const float* __restrict__ csq, const float* __restrict__ tau) {
    __shared__ __align__(16) char smem[SMEM_SZ];
    const uint32_t smb = smem_u32(smem);
    const int tid = threadIdx.x, lane = tid & 31, w = tid >> 5;
    const int wy = w >> 1, wx = w & 1;
    const int nb0 = blockIdx.x * 64, bm0 = blockIdx.y * 128;
    const float invtau = 1.0f / tau[0];
    float* csq_s = (float*)(smem + SMISC);
    if (tid < 64) csq_s[tid] = csq[nb0 + tid] * invtau;

    float acc[2][4][4];
    #pragma unroll
    for (int i = 0; i < 2; i++)
        #pragma unroll
        for (int j = 0; j < 4; j++)
            #pragma unroll
            for (int h = 0; h < 4; h++) acc[i][j][h] = 0.f;

    cpasync_B(smb, SB0, cbh, cbl, nb0, D_N, 0, tid);
    CP_COMMIT();
    uint4 rah[2], ral[2];
    #pragma unroll
    for (int i = 0; i < 2; i++) {
        int idx = tid + i * 256, row = idx >> 2, seg = idx & 3;
        size_t o = ((size_t)(bm0 + row) * D_N + seg * 8) >> 3;
        rah[i] = ((const uint4*)g_zr_hi)[o];
        ral[i] = ((const uint4*)g_zr_lo)[o];
    }

    for (int kc = 0; kc < 16; kc++) {
        // Barrier FIRST: everyone must be done reading SA and SB[(kc+1)&1]
        // (from compute kc-1) before cp.async/stores may touch them.
        __syncthreads();
        if (kc + 1 < 16) {
            cpasync_B(smb, ((kc + 1) & 1) ? SB1 : SB0, cbh, cbl, nb0, D_N, kc + 1, tid);
            CP_COMMIT();
        }
        #pragma unroll
        for (int i = 0; i < 2; i++) {
            int idx = tid + i * 256, row = idx >> 2, seg = idx & 3;
            *(uint4*)(smem + SA_HI + row * 80 + seg * 16) = rah[i];
            *(uint4*)(smem + SA_LO + row * 80 + seg * 16) = ral[i];
        }
        if (kc + 1 < 16) CP_WAIT1(); else CP_WAIT0();
        __syncthreads();
        if (kc + 1 < 16) {
            #pragma unroll
            for (int i = 0; i < 2; i++) {
                int idx = tid + i * 256, row = idx >> 2, seg = idx & 3;
                size_t o = ((size_t)(bm0 + row) * D_N + (kc + 1) * 32 + seg * 8) >> 3;
                rah[i] = ((const uint4*)g_zr_hi)[o];
                ral[i] = ((const uint4*)g_zr_lo)[o];
            }
        }
        compute_chunk(acc, smb, (kc & 1) ? SB1 : SB0, wy, wx, lane);
    }

    const float c2 = 2.0f * invtau;
    #pragma unroll
    for (int i = 0; i < 2; i++) {
        #pragma unroll
        for (int h = 0; h < 2; h++) {
            int r = bm0 + wy * 32 + i * 16 + (lane >> 2) + h * 8;
            float s = 0.f;
            #pragma unroll
            for (int j = 0; j < 4; j++) {
                int cl = wx * 32 + j * 8 + ((lane & 3) << 1);
                float e0 = __expf(fmaf(acc[i][j][h * 2],     c2, -csq_s[cl]));
                float e1 = __expf(fmaf(acc[i][j][h * 2 + 1], c2, -csq_s[cl + 1]));
                s += e0 + e1;
                *(float2*)&g_E[(size_t)r * K_N + nb0 + cl] = make_float2(e0, e1);
            }
            s += __shfl_xor_sync(0xffffffffu, s, 1);
            s += __shfl_xor_sync(0xffffffffu, s, 2);
            if ((lane & 3) == 0)
                g_Spart[(size_t)(blockIdx.x * 2 + wx) * B_N + r] = s;
        }
    }
}

// ---------------- kernel B ----------------
// mode 0: srcA=z0 (K=512), B=W -> g_zr(+hi/lo)
// mode 1: srcA=g_E (K=1024), normalize, nblk0 writes p; B=cbT -> out_z, g_zr -= z
__global__ void __launch_bounds__(256, 2)
out_gemm_kernel(const float* __restrict__ srcA, int strideA, int NC,
                const __nv_bfloat16* __restrict__ Bh, const __nv_bfloat16* __restrict__ Bl,
                int strideB, float* __restrict__ pout, float* __restrict__ out_z, int mode) {
    __shared__ __align__(16) char smem[SMEM_SZ];
    const uint32_t smb = smem_u32(smem);
    const int tid = threadIdx.x, lane = tid & 31, w = tid >> 5;
    const int wy = w >> 1, wx = w & 1;
    const int nb0 = blockIdx.x * 64, bm0 = blockIdx.y * 128;
    const float* A_src = mode ? g_E : srcA;
    float* invs = (float*)(smem + SMISC);
    if (mode && tid < 128) {
        float s = 0.f;
        #pragma unroll
        for (int p = 0; p < 32; p++) s += g_Spart[(size_t)p * B_N + bm0 + tid];
        invs[tid] = 1.0f / s;
    }
    float* pw = (mode && blockIdx.x == 0) ? pout : nullptr;

    float acc[2][4][4];
    #pragma unroll
    for (int i = 0; i < 2; i++)
        #pragma unroll
        for (int j = 0; j < 4; j++)
            #pragma unroll
            for (int h = 0; h < 4; h++) acc[i][j][h] = 0.f;

    cpasync_B(smb, SB0, Bh, Bl, nb0, strideB, 0, tid);
    CP_COMMIT();
    float4 raf[4];
    #pragma unroll
    for (int i = 0; i < 4; i++) {
        int idx = tid + i * 256, row = idx >> 3, seg = idx & 7;
        raf[i] = *(const float4*)&A_src[(size_t)(bm0 + row) * strideA + seg * 4];
    }

    for (int kc = 0; kc < NC; kc++) {
        // Barrier FIRST (see logits_kernel): protects SA stores and the
        // cp.async target buffer from racing compute(kc-1) readers.
        __syncthreads();
        if (kc + 1 < NC) {
            cpasync_B(smb, ((kc + 1) & 1) ? SB1 : SB0, Bh, Bl, nb0, strideB, kc + 1, tid);
            CP_COMMIT();
        }
        #pragma unroll
        for (int i = 0; i < 4; i++) {
            int idx = tid + i * 256, row = idx >> 3, seg = idx & 7;
            float4 v = raf[i];
            if (mode) {
                float s = invs[row];
                v.x *= s; v.y *= s; v.z *= s; v.w *= s;
                if (pw)
                    *(float4*)&pw[(size_t)(bm0 + row) * K_N + kc * 32 + seg * 4] = v;
            }
            float hx = bfr(v.x), hy = bfr(v.y), hz = bfr(v.z), hw = bfr(v.w);
            *(uint2*)(smem + SA_HI + row * 80 + seg * 8) =
                make_uint2(pack2(hx, hy), pack2(hz, hw));
            *(uint2*)(smem + SA_LO + row * 80 + seg * 8) =
                make_uint2(pack2(v.x - hx, v.y - hy), pack2(v.z - hz, v.w - hw));
        }
        if (kc + 1 < NC) CP_WAIT1(); else CP_WAIT0();
        __syncthreads();
        if (kc + 1 < NC) {
            #pragma unroll
            for (int i = 0; i < 4; i++) {
                int idx = tid + i * 256, row = idx >> 3, seg = idx & 7;
                raf[i] = *(const float4*)&A_src[(size_t)(bm0 + row) * strideA
                                                + (kc + 1) * 32 + seg * 4];
            }
        }
        compute_chunk(acc, smb, (kc & 1) ? SB1 : SB0, wy, wx, lane);
    }

    #pragma unroll
    for (int i = 0; i < 2; i++)
        #pragma unroll
        for (int j = 0; j < 4; j++)
            #pragma unroll
            for (int h = 0; h < 2; h++) {
                int r = bm0 + wy * 32 + i * 16 + (lane >> 2) + h * 8;
                int col = nb0 + wx * 32 + j * 8 + ((lane & 3) << 1);
                size_t g = (size_t)r * D_N + col;
                float v0 = acc[i][j][h * 2], v1 = acc[i][j][h * 2 + 1];
                float2 nr;
                if (mode) {
                    float2 old = *(const float2*)&g_zr[g];
                    *(float2*)&out_z[g] = make_float2(v0, v1);
                    nr = make_float2(old.x - v0, old.y - v1);
                } else {
                    nr = make_float2(v0, v1);
                }
                *(float2*)&g_zr[g] = nr;
                float hx = bfr(nr.x), hy = bfr(nr.y);
                *(uint32_t*)&g_zr_hi[g] = pack2(hx, hy);
                *(uint32_t*)&g_zr_lo[g] = pack2(nr.x - hx, nr.y - hy);
            }
}

// ---------------- launch ----------------
extern "C" void kernel_launch(void* const* d_in, const int* in_sizes, int n_in,
                              void* d_out, int out_size)
{
    const float* z0   = (const float*)d_in[0];
    const float* tau  = (const float*)d_in[1];
    const float* W    = (const float*)d_in[2];
    const float* cbks = (const float*)d_in[3];
    float* out   = (float*)d_out;
    float* out_z = out;
    float* out_p = out + (size_t)L_N * B_N * D_N;

    __nv_bfloat16 *wh, *wl, *ch, *cl, *cth, *ctl;
    float* csq_p;
    cudaGetSymbolAddress((void**)&wh, g_W_hi);
    cudaGetSymbolAddress((void**)&wl, g_W_lo);
    cudaGetSymbolAddress((void**)&ch, g_cb_hi);
    cudaGetSymbolAddress((void**)&cl, g_cb_lo);
    cudaGetSymbolAddress((void**)&cth, g_cbT_hi);
    cudaGetSymbolAddress((void**)&ctl, g_cbT_lo);
    cudaGetSymbolAddress((void**)&csq_p, g_csq);

    split_kernel<<<(D_N * D_N) / 256, 256>>>(W, wh, wl, D_N * D_N);
    split_kernel<<<(L_N * K_N * D_N) / 256, 256>>>(cbks, ch, cl, L_N * K_N * D_N);
    tsplit_kernel<<<dim3(K_N / 32, D_N / 32, L_N), dim3(32, 8)>>>(cbks);
    csq_kernel<<<(L_N * K_N) / 8, 256>>>(cbks);

    // whitening: g_zr = z0 @ W^T
    out_gemm_kernel<<<dim3(8, 256), 256>>>(z0, D_N, 16, wh, wl, D_N,
                                           nullptr, nullptr, 0);
    for (int l = 0; l < L_N; l++) {
        logits_kernel<<<dim3(16, 256), 256>>>(
            ch + (size_t)l * K_N * D_N, cl + (size_t)l * K_N * D_N,
            csq_p + l * K_N, tau);
        out_gemm_kernel<<<dim3(8, 256), 256>>>(
            nullptr, K_N, 32,
            cth + (size_t)l * D_N * K_N, ctl + (size_t)l * D_N * K_N, K_N,
            out_p + (size_t)l * B_N * K_N, out_z + (size_t)l * B_N * D_N, 1);
    }
}